// round 5
// baseline (speedup 1.0000x reference)
#include <cuda_runtime.h>
#include <cuda_bf16.h>
#include <cstdint>

#define C_DIM 256
#define BD    128
#define CN    128
#define KREAL 784
#define KP    832           // padded K (13 * 64)
#define ALPHA 32.0f

// Split bf16 scratch for layernormed x: [C][BD][KP] hi/lo (54.5MB each)
#define NU4 3407872
__device__ uint4 g_xh[NU4];
__device__ uint4 g_xl[NU4];
__device__ float g_xn[2 * C_DIM * BD];   // |x|^2 partials per (c, bd)
__device__ int   g_ctr;                  // work-queue counter (reset by ln_split)

__device__ __forceinline__ uint32_t smem_u32(const void* p) {
    uint32_t a;
    asm("{ .reg .u64 t; cvta.to.shared.u64 t, %1; cvt.u32.u64 %0, t; }" : "=r"(a) : "l"(p));
    return a;
}

#define SWZ(off) ((off) ^ (((off) >> 3) & 0x70))

#define CP16(dst, src) \
    asm volatile("cp.async.cg.shared.global [%0], [%1], 16;" :: "r"(dst), "l"(src))
#define CP_COMMIT() asm volatile("cp.async.commit_group;" ::: "memory")

#define LDSM4(r0, r1, r2, r3, addr) \
    asm volatile("ldmatrix.sync.aligned.m8n8.x4.shared.b16 {%0,%1,%2,%3}, [%4];" \
                 : "=r"(r0), "=r"(r1), "=r"(r2), "=r"(r3) : "r"(addr))

#define MMA16816(d, a, b) \
    asm volatile("mma.sync.aligned.m16n8k16.row.col.f32.bf16.bf16.f32 " \
                 "{%0,%1,%2,%3},{%4,%5,%6,%7},{%8,%9},{%0,%1,%2,%3};" \
                 : "+f"((d)[0]), "+f"((d)[1]), "+f"((d)[2]), "+f"((d)[3]) \
                 : "r"((a)[0]), "r"((a)[1]), "r"((a)[2]), "r"((a)[3]), \
                   "r"((b)[0]), "r"((b)[1]))

// ---------------------------------------------------------------------------
// Kernel 1: LayerNorm over C + transpose + bf16 hi/lo split + |x|^2 partials.
// grid (BD, 2). Wide 16B packed stores.
// ---------------------------------------------------------------------------
__global__ void ln_split_kernel(const float* __restrict__ x,
                                const float* __restrict__ lnw,
                                const float* __restrict__ lnb) {
    __shared__ float s[32][C_DIM + 1];
    int bd   = blockIdx.x;
    int part = blockIdx.y;
    int lane = threadIdx.x & 31;
    int warp = threadIdx.x >> 5;
    if (bd == 0 && part == 0 && threadIdx.x == 0) g_ctr = 0;

    float nacc[4] = {0.f, 0.f, 0.f, 0.f};
    __nv_bfloat16* xh = (__nv_bfloat16*)g_xh;
    __nv_bfloat16* xl = (__nv_bfloat16*)g_xl;

    for (int tile = part * 13; tile < part * 13 + 13; tile++) {
        int hw0 = tile * 32;
        #pragma unroll
        for (int i = 0; i < 4; i++) {
            int p  = warp * 4 + i;
            int hw = hw0 + p;
            int c0 = lane * 4, c1 = 128 + lane * 4;
            if (hw < KREAL) {
                const float4* row = (const float4*)(x + ((size_t)bd * KREAL + hw) * C_DIM);
                float4 v0 = row[lane];
                float4 v1 = row[lane + 32];
                float s1 = v0.x + v0.y + v0.z + v0.w + v1.x + v1.y + v1.z + v1.w;
                float s2 = v0.x*v0.x + v0.y*v0.y + v0.z*v0.z + v0.w*v0.w
                         + v1.x*v1.x + v1.y*v1.y + v1.z*v1.z + v1.w*v1.w;
                #pragma unroll
                for (int o = 16; o > 0; o >>= 1) {
                    s1 += __shfl_xor_sync(0xffffffffu, s1, o);
                    s2 += __shfl_xor_sync(0xffffffffu, s2, o);
                }
                float mean = s1 * (1.0f / C_DIM);
                float var  = s2 * (1.0f / C_DIM) - mean * mean;
                float rs   = rsqrtf(var + 1e-5f);
                s[p][c0+0] = (v0.x - mean) * rs * lnw[c0+0] + lnb[c0+0];
                s[p][c0+1] = (v0.y - mean) * rs * lnw[c0+1] + lnb[c0+1];
                s[p][c0+2] = (v0.z - mean) * rs * lnw[c0+2] + lnb[c0+2];
                s[p][c0+3] = (v0.w - mean) * rs * lnw[c0+3] + lnb[c0+3];
                s[p][c1+0] = (v1.x - mean) * rs * lnw[c1+0] + lnb[c1+0];
                s[p][c1+1] = (v1.y - mean) * rs * lnw[c1+1] + lnb[c1+1];
                s[p][c1+2] = (v1.z - mean) * rs * lnw[c1+2] + lnb[c1+2];
                s[p][c1+3] = (v1.w - mean) * rs * lnw[c1+3] + lnb[c1+3];
            } else {
                #pragma unroll
                for (int e = 0; e < 4; e++) { s[p][c0+e] = 0.0f; s[p][c1+e] = 0.0f; }
            }
        }
        __syncthreads();

        #pragma unroll
        for (int pass = 0; pass < 4; pass++) {
            int c  = warp * 32 + pass * 8 + (lane >> 2);
            int h0 = (lane & 3) * 8;
            unsigned short hs[8], ls[8];
            #pragma unroll
            for (int h = 0; h < 8; h++) {
                float v = s[h0 + h][c];
                nacc[pass] = fmaf(v, v, nacc[pass]);
                __nv_bfloat16 hb = __float2bfloat16(v);
                hs[h] = __bfloat16_as_ushort(hb);
                ls[h] = __bfloat16_as_ushort(__float2bfloat16(v - __bfloat162float(hb)));
            }
            size_t idx = (size_t)c * (BD * KP) + (size_t)bd * KP + hw0 + h0;
            *(uint4*)(xh + idx) = *(uint4*)hs;
            *(uint4*)(xl + idx) = *(uint4*)ls;
        }
        __syncthreads();
    }

    #pragma unroll
    for (int pass = 0; pass < 4; pass++) {
        float v = nacc[pass];
        v += __shfl_xor_sync(0xffffffffu, v, 1);
        v += __shfl_xor_sync(0xffffffffu, v, 2);
        if ((lane & 3) == 0) {
            int c = warp * 32 + pass * 8 + (lane >> 2);
            g_xn[(size_t)part * (C_DIM * BD) + (size_t)c * BD + bd] = v;
        }
    }
}

// ---------------------------------------------------------------------------
// Persistent distance GEMM + fused softmax. Work queue: 4 slices per c:
//   r 0,1: x-dist  m=cn(128) x n=bd(64, half r).  A = cc (fp32->hi/lo in-kernel),
//          B = x (cp.async from split scratch). Epilogue: dist + softmax.
//   r 2:   cc-dist top slab m=64(rows 0-63) x n=128. Writes slab + transpose.
//   r 3:   cc-dist corner m=n=64 (rows/cols 64-127).
// cc converted in-GEMM with register prefetch; |cc|^2 norms free at conversion.
// ---------------------------------------------------------------------------
#define STAGE 49152
#define CVH 0
#define CVL 16384
#define XBH 32768
#define XBL 40960

template <int NT, int XD, int NR>
__device__ __forceinline__ void run_slice(
    uint32_t sbA, char* smA, float* sCn, float* sXn,
    const float* __restrict__ cc, float* __restrict__ out,
    int c, int n0, int r0, int t)
{
    const size_t OUT1 = (size_t)BD * C_DIM * CN;
    int lane = t & 31, w = t >> 5;
    int wm = XD ? w * 16 : (w >> 1) * 16;
    int wn = XD ? 0 : (NT == 8 ? (w & 1) * 64 : (w & 1) * 32);

    const float* Ag = cc + ((size_t)c * CN + r0) * KREAL;
    int crow = t >> 4, ccol = t & 15;
    constexpr int NJ = NR / 16;

    if (XD && t < 64)
        sXn[t] = g_xn[(size_t)c * BD + n0 + t]
               + g_xn[C_DIM * BD + (size_t)c * BD + n0 + t];

    const uint4* Bh = g_xh + (size_t)c * 13312 + (size_t)n0 * 104;
    const uint4* Bl = g_xl + (size_t)c * 13312 + (size_t)n0 * 104;

    float4 av[NJ];
    float cnrm[NJ];
    #pragma unroll
    for (int j = 0; j < NJ; j++) cnrm[j] = 0.f;

    auto ldgA = [&](int kt) {
        bool kv = (kt < 12) || (ccol < 4);
        #pragma unroll
        for (int j = 0; j < NJ; j++) {
            int lr = crow + 16 * j;
            av[j] = kv ? *(const float4*)(Ag + (size_t)lr * KREAL + kt * 64 + ccol * 4)
                       : make_float4(0.f, 0.f, 0.f, 0.f);
        }
    };
    auto stsA = [&](int s) {
        char* base = smA + s * STAGE;
        #pragma unroll
        for (int j = 0; j < NJ; j++) {
            int lr = crow + 16 * j;
            float4 v = av[j];
            cnrm[j] += v.x*v.x + v.y*v.y + v.z*v.z + v.w*v.w;
            __nv_bfloat16 h0 = __float2bfloat16(v.x);
            __nv_bfloat16 h1 = __float2bfloat16(v.y);
            __nv_bfloat16 h2 = __float2bfloat16(v.z);
            __nv_bfloat16 h3 = __float2bfloat16(v.w);
            uint2 hu, lu;
            hu.x = (uint32_t)__bfloat16_as_ushort(h0) | ((uint32_t)__bfloat16_as_ushort(h1) << 16);
            hu.y = (uint32_t)__bfloat16_as_ushort(h2) | ((uint32_t)__bfloat16_as_ushort(h3) << 16);
            __nv_bfloat16 l0 = __float2bfloat16(v.x - __bfloat162float(h0));
            __nv_bfloat16 l1 = __float2bfloat16(v.y - __bfloat162float(h1));
            __nv_bfloat16 l2 = __float2bfloat16(v.z - __bfloat162float(h2));
            __nv_bfloat16 l3 = __float2bfloat16(v.w - __bfloat162float(h3));
            lu.x = (uint32_t)__bfloat16_as_ushort(l0) | ((uint32_t)__bfloat16_as_ushort(l1) << 16);
            lu.y = (uint32_t)__bfloat16_as_ushort(l2) | ((uint32_t)__bfloat16_as_ushort(l3) << 16);
            uint32_t off = SWZ((uint32_t)(lr * 128 + ccol * 8));
            *(uint2*)(base + CVH + off) = hu;
            *(uint2*)(base + CVL + off) = lu;
        }
    };
    auto cpB = [&](int kt, int s) {
        if (XD) {
            uint32_t base = sbA + (uint32_t)s * STAGE;
            #pragma unroll
            for (int j = 0; j < 2; j++) {
                int idx = j * 256 + t;
                int row = idx >> 3, ch = idx & 7;
                size_t go = (size_t)row * 104 + (size_t)kt * 8 + ch;
                uint32_t so = SWZ((uint32_t)idx * 16);
                CP16(base + XBH + so, (const void*)(Bh + go));
                CP16(base + XBL + so, (const void*)(Bl + go));
            }
        }
        CP_COMMIT();
    };

    float acc[NT][4];
    #pragma unroll
    for (int j = 0; j < NT; j++)
        #pragma unroll
        for (int e = 0; e < 4; e++) acc[j][e] = 0.0f;

    ldgA(0); cpB(0, 0); stsA(0);
    ldgA(1); cpB(1, 1); stsA(1);

    const uint32_t bbase = XD ? XBH : CVH;
    const uint32_t blo   = XD ? (XBL - XBH) : (CVL - CVH);
    const uint32_t arow  = (uint32_t)(wm + (lane & 15));

    for (int i = 0; i < 13; i++) {
        if (i + 2 < 13) ldgA(i + 2);
        if (i < 12) asm volatile("cp.async.wait_group 1;" ::: "memory");
        else        asm volatile("cp.async.wait_group 0;" ::: "memory");
        __syncthreads();

        uint32_t base = sbA + (uint32_t)(i & 1) * STAGE;
        #pragma unroll
        for (int ks = 0; ks < 4; ks++) {
            uint32_t ah[4], al[4], bb[NT][2];
            uint32_t kbA = (uint32_t)ks * 32 + ((lane & 16) ? 16u : 0u);
            uint32_t aA  = base + CVH + SWZ(arow * 128 + kbA);
            LDSM4(ah[0], ah[1], ah[2], ah[3], aA);
            LDSM4(al[0], al[1], al[2], al[3], aA + (CVL - CVH));

            uint32_t kbB = (uint32_t)ks * 32 + ((lane & 8) ? 16u : 0u);
            uint32_t rB  = (uint32_t)(wn + ((lane & 16) ? 8 : 0) + (lane & 7));
            uint32_t aB  = base + bbase + SWZ(rB * 128 + kbB);
            #pragma unroll
            for (int p = 0; p < NT / 2; p++)
                LDSM4(bb[2*p][0], bb[2*p][1], bb[2*p+1][0], bb[2*p+1][1], aB + p * 2048);

            #pragma unroll
            for (int nt = 0; nt < NT; nt++) MMA16816(acc[nt], ah, bb[nt]);
            #pragma unroll
            for (int nt = 0; nt < NT; nt++) MMA16816(acc[nt], al, bb[nt]);

            uint32_t aB2 = aB + blo;
            #pragma unroll
            for (int p = 0; p < NT / 2; p++)
                LDSM4(bb[2*p][0], bb[2*p][1], bb[2*p+1][0], bb[2*p+1][1], aB2 + p * 2048);
            #pragma unroll
            for (int nt = 0; nt < NT; nt++) MMA16816(acc[nt], ah, bb[nt]);
        }
        __syncthreads();
        if (i + 2 < 13) { cpB(i + 2, i & 1); stsA(i & 1); }
    }

    // cc row norms from conversion pass.
    #pragma unroll
    for (int j = 0; j < NJ; j++) {
        float v = cnrm[j];
        v += __shfl_xor_sync(0xffffffffu, v, 1);
        v += __shfl_xor_sync(0xffffffffu, v, 2);
        v += __shfl_xor_sync(0xffffffffu, v, 4);
        v += __shfl_xor_sync(0xffffffffu, v, 8);
        if (ccol == 0) sCn[crow + 16 * j] = v;
    }
    __syncthreads();

    // Distances -> ebuf[n][m]
    float* ebuf = (float*)smA;
    constexpr int PITCH = XD ? 132 : 68;
    #pragma unroll
    for (int nt = 0; nt < NT; nt++) {
        #pragma unroll
        for (int e = 0; e < 4; e++) {
            int m = wm + (lane >> 2) + ((e >> 1) << 3);
            int n = wn + nt * 8 + ((lane & 3) << 1) + (e & 1);
            float bn = XD ? sXn[n] : sCn[n];
            float d2 = sCn[m] + bn - 2.0f * acc[nt][e];
            ebuf[n * PITCH + m] = sqrtf(fmaxf(d2, 1e-12f));
        }
    }
    __syncthreads();

    if (XD) {
        // x_distance writes [bd][c][cn]
        #pragma unroll
        for (int j = 0; j < 8; j++) {
            int idx = j * 256 + t;
            int n = idx >> 5, q = idx & 31;
            float4 v = *(const float4*)&ebuf[n * 132 + q * 4];
            *(float4*)(out + ((size_t)(n0 + n) * C_DIM + c) * CN + q * 4) = v;
        }
        // fused softmax over cn for each bd row
        float* aout = out + OUT1;
        #pragma unroll
        for (int rj = 0; rj < 8; rj++) {
            int r = w * 8 + rj;
            float4 v = *(const float4*)&ebuf[r * 132 + lane * 4];
            float mn = fminf(fminf(v.x, v.y), fminf(v.z, v.w));
            #pragma unroll
            for (int o = 16; o > 0; o >>= 1) mn = fminf(mn, __shfl_xor_sync(0xffffffffu, mn, o));
            float e0 = __expf(-ALPHA * (v.x - mn));
            float e1 = __expf(-ALPHA * (v.y - mn));
            float e2 = __expf(-ALPHA * (v.z - mn));
            float e3 = __expf(-ALPHA * (v.w - mn));
            float sum = e0 + e1 + e2 + e3;
            #pragma unroll
            for (int o = 16; o > 0; o >>= 1) sum += __shfl_xor_sync(0xffffffffu, sum, o);
            float inv = 1.0f / sum;
            *(float4*)(aout + ((size_t)(n0 + r) * C_DIM + c) * CN + lane * 4) =
                make_float4(e0 * inv, e1 * inv, e2 * inv, e3 * inv);
        }
    } else if (NT == 8) {
        // top slab: rows 0-63 x cols 0-127; write [n][m] + transpose into cols 64-127
        float* o2 = out + 2 * OUT1 + (size_t)c * (CN * CN);
        #pragma unroll
        for (int j = 0; j < 8; j++) {
            int idx = j * 256 + t;
            int n = idx >> 4, q = idx & 15;
            *(float4*)(o2 + (size_t)n * CN + q * 4) = *(const float4*)&ebuf[n * 68 + q * 4];
        }
        #pragma unroll
        for (int jj = 0; jj < 16; jj++) {
            int idx = jj * 256 + t;
            int m = idx >> 6, nn = 64 + (idx & 63);
            o2[(size_t)m * CN + nn] = ebuf[nn * 68 + m];
        }
    } else {
        // corner block: rows/cols 64-127
        float* o2 = out + 2 * OUT1 + (size_t)c * (CN * CN);
        #pragma unroll
        for (int j = 0; j < 4; j++) {
            int idx = j * 256 + t;
            int n = idx >> 4, q = idx & 15;
            *(float4*)(o2 + (size_t)(64 + n) * CN + 64 + q * 4) = *(const float4*)&ebuf[n * 68 + q * 4];
        }
    }
}

__global__ void __launch_bounds__(256, 2)
dist_gemm_all(const float* __restrict__ cc, float* __restrict__ out) {
    extern __shared__ char dsm[];
    __shared__ int s_ws;
    uint32_t sb0 = smem_u32(dsm);
    uint32_t sbA = (sb0 + 1023u) & ~1023u;
    char* smA = dsm + (sbA - sb0);
    float* sCn = (float*)(smA + 2 * STAGE);
    float* sXn = sCn + 128;
    int t = threadIdx.x;

    while (true) {
        if (t == 0) s_ws = atomicAdd(&g_ctr, 1);
        __syncthreads();
        int ws = s_ws;
        if (ws >= 1024) break;
        int c = ws >> 2, r = ws & 3;
        if (r < 2)
            run_slice<8, 1, 128>(sbA, smA, sCn, sXn, cc, out, c, r * 64, 0, t);
        else if (r == 2)
            run_slice<8, 0, 128>(sbA, smA, sCn, sXn, cc, out, c, 0, 0, t);
        else
            run_slice<4, 0, 64>(sbA, smA, sCn, sXn, cc, out, c, 0, 64, t);
    }
}

// ---------------------------------------------------------------------------
extern "C" void kernel_launch(void* const* d_in, const int* in_sizes, int n_in,
                              void* d_out, int out_size) {
    const float* x   = (const float*)d_in[0];
    const float* lnw = (const float*)d_in[1];
    const float* lnb = (const float*)d_in[2];
    const float* cc  = (const float*)d_in[3];
    float* out = (float*)d_out;

    const int SMEM = 2 * STAGE + 768 + 1024;   // 100,096 B

    cudaFuncSetAttribute(dist_gemm_all, cudaFuncAttributeMaxDynamicSharedMemorySize, SMEM);

    ln_split_kernel<<<dim3(BD, 2), 256>>>(x, lnw, lnb);
    dist_gemm_all<<<304, 256, SMEM>>>(cc, out);
}

// round 6
// speedup vs baseline: 1.0172x; 1.0172x over previous
#include <cuda_runtime.h>
#include <cuda_bf16.h>
#include <cstdint>

#define C_DIM 256
#define BD    128
#define CN    128
#define KREAL 784
#define KP    832           // padded K (13 * 64)
#define ALPHA 32.0f

// Split bf16 scratch: [C][128][KP] hi/lo for x and cc (54.5MB each)
#define NU4 3407872
__device__ uint4 g_xh[NU4];
__device__ uint4 g_xl[NU4];
__device__ uint4 g_ch[NU4];
__device__ uint4 g_cl[NU4];
__device__ float g_xn[2 * C_DIM * BD];   // |x|^2 partials per (c, bd)
__device__ float g_cn[C_DIM * CN];       // |cc|^2 per (c, cn)
__device__ int   g_ctr;                  // work queue (reset by ln_split)

__device__ __forceinline__ uint32_t smem_u32(const void* p) {
    uint32_t a;
    asm("{ .reg .u64 t; cvta.to.shared.u64 t, %1; cvt.u32.u64 %0, t; }" : "=r"(a) : "l"(p));
    return a;
}

#define SWZ(off) ((off) ^ (((off) >> 3) & 0x70))

#define CP16(dst, src) \
    asm volatile("cp.async.cg.shared.global [%0], [%1], 16;" :: "r"(dst), "l"(src))
#define CP_COMMIT() asm volatile("cp.async.commit_group;" ::: "memory")

#define LDSM4(r0, r1, r2, r3, addr) \
    asm volatile("ldmatrix.sync.aligned.m8n8.x4.shared.b16 {%0,%1,%2,%3}, [%4];" \
                 : "=r"(r0), "=r"(r1), "=r"(r2), "=r"(r3) : "r"(addr))

#define MMA16816(d, a, b) \
    asm volatile("mma.sync.aligned.m16n8k16.row.col.f32.bf16.bf16.f32 " \
                 "{%0,%1,%2,%3},{%4,%5,%6,%7},{%8,%9},{%0,%1,%2,%3};" \
                 : "+f"((d)[0]), "+f"((d)[1]), "+f"((d)[2]), "+f"((d)[3]) \
                 : "r"((a)[0]), "r"((a)[1]), "r"((a)[2]), "r"((a)[3]), \
                   "r"((b)[0]), "r"((b)[1]))

// ---------------------------------------------------------------------------
// Kernel 1: LayerNorm over C + transpose + bf16 hi/lo split + |x|^2 partials.
// ---------------------------------------------------------------------------
__global__ void ln_split_kernel(const float* __restrict__ x,
                                const float* __restrict__ lnw,
                                const float* __restrict__ lnb) {
    __shared__ float s[32][C_DIM + 1];
    int bd   = blockIdx.x;
    int part = blockIdx.y;
    int lane = threadIdx.x & 31;
    int warp = threadIdx.x >> 5;
    if (bd == 0 && part == 0 && threadIdx.x == 0) g_ctr = 0;

    float nacc[4] = {0.f, 0.f, 0.f, 0.f};
    __nv_bfloat16* xh = (__nv_bfloat16*)g_xh;
    __nv_bfloat16* xl = (__nv_bfloat16*)g_xl;

    for (int tile = part * 13; tile < part * 13 + 13; tile++) {
        int hw0 = tile * 32;
        #pragma unroll
        for (int i = 0; i < 4; i++) {
            int p  = warp * 4 + i;
            int hw = hw0 + p;
            int c0 = lane * 4, c1 = 128 + lane * 4;
            if (hw < KREAL) {
                const float4* row = (const float4*)(x + ((size_t)bd * KREAL + hw) * C_DIM);
                float4 v0 = row[lane];
                float4 v1 = row[lane + 32];
                float s1 = v0.x + v0.y + v0.z + v0.w + v1.x + v1.y + v1.z + v1.w;
                float s2 = v0.x*v0.x + v0.y*v0.y + v0.z*v0.z + v0.w*v0.w
                         + v1.x*v1.x + v1.y*v1.y + v1.z*v1.z + v1.w*v1.w;
                #pragma unroll
                for (int o = 16; o > 0; o >>= 1) {
                    s1 += __shfl_xor_sync(0xffffffffu, s1, o);
                    s2 += __shfl_xor_sync(0xffffffffu, s2, o);
                }
                float mean = s1 * (1.0f / C_DIM);
                float var  = s2 * (1.0f / C_DIM) - mean * mean;
                float rs   = rsqrtf(var + 1e-5f);
                s[p][c0+0] = (v0.x - mean) * rs * lnw[c0+0] + lnb[c0+0];
                s[p][c0+1] = (v0.y - mean) * rs * lnw[c0+1] + lnb[c0+1];
                s[p][c0+2] = (v0.z - mean) * rs * lnw[c0+2] + lnb[c0+2];
                s[p][c0+3] = (v0.w - mean) * rs * lnw[c0+3] + lnb[c0+3];
                s[p][c1+0] = (v1.x - mean) * rs * lnw[c1+0] + lnb[c1+0];
                s[p][c1+1] = (v1.y - mean) * rs * lnw[c1+1] + lnb[c1+1];
                s[p][c1+2] = (v1.z - mean) * rs * lnw[c1+2] + lnb[c1+2];
                s[p][c1+3] = (v1.w - mean) * rs * lnw[c1+3] + lnb[c1+3];
            } else {
                #pragma unroll
                for (int e = 0; e < 4; e++) { s[p][c0+e] = 0.0f; s[p][c1+e] = 0.0f; }
            }
        }
        __syncthreads();

        #pragma unroll
        for (int pass = 0; pass < 4; pass++) {
            int c  = warp * 32 + pass * 8 + (lane >> 2);
            int h0 = (lane & 3) * 8;
            unsigned short hs[8], ls[8];
            #pragma unroll
            for (int h = 0; h < 8; h++) {
                float v = s[h0 + h][c];
                nacc[pass] = fmaf(v, v, nacc[pass]);
                __nv_bfloat16 hb = __float2bfloat16(v);
                hs[h] = __bfloat16_as_ushort(hb);
                ls[h] = __bfloat16_as_ushort(__float2bfloat16(v - __bfloat162float(hb)));
            }
            size_t idx = (size_t)c * (BD * KP) + (size_t)bd * KP + hw0 + h0;
            *(uint4*)(xh + idx) = *(uint4*)hs;
            *(uint4*)(xl + idx) = *(uint4*)ls;
        }
        __syncthreads();
    }

    #pragma unroll
    for (int pass = 0; pass < 4; pass++) {
        float v = nacc[pass];
        v += __shfl_xor_sync(0xffffffffu, v, 1);
        v += __shfl_xor_sync(0xffffffffu, v, 2);
        if ((lane & 3) == 0) {
            int c = warp * 32 + pass * 8 + (lane >> 2);
            g_xn[(size_t)part * (C_DIM * BD) + (size_t)c * BD + bd] = v;
        }
    }
}

// ---------------------------------------------------------------------------
// Kernel 2: cc fp32 -> bf16 hi/lo split + pad + |cc|^2. One warp per row.
// ---------------------------------------------------------------------------
__global__ void cc_split_kernel(const float* __restrict__ cc) {
    int row  = blockIdx.x * 8 + (threadIdx.x >> 5);
    int lane = threadIdx.x & 31;
    const float4* src = (const float4*)(cc + (size_t)row * KREAL);
    __nv_bfloat16* ch = (__nv_bfloat16*)g_ch;
    __nv_bfloat16* cl = (__nv_bfloat16*)g_cl;
    float ssq = 0.0f;
    #pragma unroll
    for (int i = 0; i < 7; i++) {
        int k4 = lane + 32 * i;
        if (k4 >= KP / 4) break;
        float4 v = (k4 < KREAL / 4) ? src[k4] : make_float4(0.f, 0.f, 0.f, 0.f);
        ssq += v.x*v.x + v.y*v.y + v.z*v.z + v.w*v.w;
        ushort4 hs, ls;
        float e; __nv_bfloat16 h;
        e = v.x; h = __float2bfloat16(e); hs.x = __bfloat16_as_ushort(h);
        ls.x = __bfloat16_as_ushort(__float2bfloat16(e - __bfloat162float(h)));
        e = v.y; h = __float2bfloat16(e); hs.y = __bfloat16_as_ushort(h);
        ls.y = __bfloat16_as_ushort(__float2bfloat16(e - __bfloat162float(h)));
        e = v.z; h = __float2bfloat16(e); hs.z = __bfloat16_as_ushort(h);
        ls.z = __bfloat16_as_ushort(__float2bfloat16(e - __bfloat162float(h)));
        e = v.w; h = __float2bfloat16(e); hs.w = __bfloat16_as_ushort(h);
        ls.w = __bfloat16_as_ushort(__float2bfloat16(e - __bfloat162float(h)));
        size_t o = (size_t)row * KP + (size_t)k4 * 4;
        *(ushort4*)(ch + o) = hs;
        *(ushort4*)(cl + o) = ls;
    }
    #pragma unroll
    for (int o = 16; o > 0; o >>= 1) ssq += __shfl_xor_sync(0xffffffffu, ssq, o);
    if (lane == 0) g_cn[row] = ssq;
}

// ---------------------------------------------------------------------------
// Persistent distance GEMM, 512 threads, full 128x128 tiles, warp grid 4x4
// (32m x 32n per warp). Queue: 2 items per c (x-dist with fused softmax,
// cc-dist). 3-term bf16 split MMA, K=832, double-buffered 64KB stages.
// ---------------------------------------------------------------------------
#define STAGE  65536
#define OF_AH  0
#define OF_AL  16384
#define OF_BH  32768
#define OF_BL  49152

template <int XD>
__device__ __forceinline__ void run_tile(
    uint32_t sbA, char* smA, float* sCn, float* sXn,
    float* __restrict__ out, int c, int t)
{
    const size_t OUT1 = (size_t)BD * C_DIM * CN;
    int lane = t & 31, w = t >> 5;
    int wm = (w & 3) * 32, wn = (w >> 2) * 32;

    size_t boff = (size_t)c * 13312;                 // 128 rows * 104 uint4
    const uint4* Ah = g_ch + boff;
    const uint4* Al = g_cl + boff;
    const uint4* Bh = XD ? g_xh + boff : Ah;
    const uint4* Bl = XD ? g_xl + boff : Al;

    if (t < 128)      sCn[t] = g_cn[(size_t)c * CN + t];
    else if (t < 256) {
        int n = t - 128;
        sXn[n] = XD ? g_xn[(size_t)c * BD + n] + g_xn[C_DIM * BD + (size_t)c * BD + n]
                    : g_cn[(size_t)c * CN + n];
    }

    auto issue = [&](int kt, int s) {
        uint32_t base = sbA + (uint32_t)s * STAGE;
        #pragma unroll
        for (int j = 0; j < 2; j++) {
            int idx = j * 512 + t;
            int row = idx >> 3, ch = idx & 7;
            size_t go = (size_t)row * 104 + (size_t)kt * 8 + ch;
            uint32_t so = SWZ((uint32_t)idx * 16);
            CP16(base + OF_AH + so, (const void*)(Ah + go));
            CP16(base + OF_AL + so, (const void*)(Al + go));
            if (XD) {
                CP16(base + OF_BH + so, (const void*)(Bh + go));
                CP16(base + OF_BL + so, (const void*)(Bl + go));
            }
        }
        CP_COMMIT();
    };

    float acc[2][4][4];
    #pragma unroll
    for (int i = 0; i < 2; i++)
        #pragma unroll
        for (int j = 0; j < 4; j++)
            #pragma unroll
            for (int e = 0; e < 4; e++) acc[i][j][e] = 0.0f;

    issue(0, 0);
    issue(1, 1);

    const uint32_t bbase = XD ? OF_BH : OF_AH;
    const uint32_t arow  = (uint32_t)(wm + (lane & 15));
    const uint32_t rB    = (uint32_t)(wn + ((lane & 16) ? 8 : 0) + (lane & 7));

    for (int i = 0; i < 13; i++) {
        if (i < 12) asm volatile("cp.async.wait_group 1;" ::: "memory");
        else        asm volatile("cp.async.wait_group 0;" ::: "memory");
        __syncthreads();

        uint32_t base = sbA + (uint32_t)(i & 1) * STAGE;
        #pragma unroll
        for (int ks = 0; ks < 4; ks++) {
            uint32_t ah[2][4], al[2][4], bh[4][2], bl[4][2];
            uint32_t kbA = (uint32_t)ks * 32 + ((lane & 16) ? 16u : 0u);
            uint32_t aA  = base + OF_AH + SWZ(arow * 128 + kbA);
            LDSM4(ah[0][0], ah[0][1], ah[0][2], ah[0][3], aA);
            LDSM4(ah[1][0], ah[1][1], ah[1][2], ah[1][3], aA + 2048);
            LDSM4(al[0][0], al[0][1], al[0][2], al[0][3], aA + (OF_AL - OF_AH));
            LDSM4(al[1][0], al[1][1], al[1][2], al[1][3], aA + (OF_AL - OF_AH) + 2048);

            uint32_t kbB = (uint32_t)ks * 32 + ((lane & 8) ? 16u : 0u);
            uint32_t aB  = base + bbase + SWZ(rB * 128 + kbB);
            LDSM4(bh[0][0], bh[0][1], bh[1][0], bh[1][1], aB);
            LDSM4(bh[2][0], bh[2][1], bh[3][0], bh[3][1], aB + 2048);
            LDSM4(bl[0][0], bl[0][1], bl[1][0], bl[1][1], aB + 16384);
            LDSM4(bl[2][0], bl[2][1], bl[3][0], bl[3][1], aB + 16384 + 2048);

            #pragma unroll
            for (int mt = 0; mt < 2; mt++)
                #pragma unroll
                for (int nt = 0; nt < 4; nt++) {
                    MMA16816(acc[mt][nt], ah[mt], bh[nt]);
                    MMA16816(acc[mt][nt], al[mt], bh[nt]);
                    MMA16816(acc[mt][nt], ah[mt], bl[nt]);
                }
        }
        __syncthreads();
        if (i + 2 < 13) issue(i + 2, i & 1);
    }

    // Distances into ebuf[n][m], pitch 132.
    float* ebuf = (float*)smA;
    #pragma unroll
    for (int mt = 0; mt < 2; mt++) {
        #pragma unroll
        for (int nt = 0; nt < 4; nt++) {
            #pragma unroll
            for (int e = 0; e < 4; e++) {
                int m = wm + mt * 16 + (lane >> 2) + ((e >> 1) << 3);
                int n = wn + nt * 8 + ((lane & 3) << 1) + (e & 1);
                float d2 = sCn[m] + sXn[n] - 2.0f * acc[mt][nt][e];
                ebuf[n * 132 + m] = sqrtf(fmaxf(d2, 1e-12f));
            }
        }
    }
    __syncthreads();

    if (XD) {
        // per warp: 8 bd rows; write x_distance + fused softmax assign
        float* aout = out + OUT1;
        #pragma unroll
        for (int rj = 0; rj < 8; rj++) {
            int r = w * 8 + rj;                      // bd
            float4 v = *(const float4*)&ebuf[r * 132 + lane * 4];
            *(float4*)(out + ((size_t)r * C_DIM + c) * CN + lane * 4) = v;
            float mn = fminf(fminf(v.x, v.y), fminf(v.z, v.w));
            #pragma unroll
            for (int o = 16; o > 0; o >>= 1) mn = fminf(mn, __shfl_xor_sync(0xffffffffu, mn, o));
            float e0 = __expf(-ALPHA * (v.x - mn));
            float e1 = __expf(-ALPHA * (v.y - mn));
            float e2 = __expf(-ALPHA * (v.z - mn));
            float e3 = __expf(-ALPHA * (v.w - mn));
            float sum = e0 + e1 + e2 + e3;
            #pragma unroll
            for (int o = 16; o > 0; o >>= 1) sum += __shfl_xor_sync(0xffffffffu, sum, o);
            float inv = 1.0f / sum;
            *(float4*)(aout + ((size_t)r * C_DIM + c) * CN + lane * 4) =
                make_float4(e0 * inv, e1 * inv, e2 * inv, e3 * inv);
        }
    } else {
        float* o2 = out + 2 * OUT1 + (size_t)c * (CN * CN);
        #pragma unroll
        for (int j = 0; j < 8; j++) {
            int idx = j * 512 + t;
            int n = idx >> 5, m4 = idx & 31;
            *(float4*)(o2 + (size_t)n * CN + m4 * 4) = *(const float4*)&ebuf[n * 132 + m4 * 4];
        }
    }
}

__global__ void __launch_bounds__(512)
dist_gemm_all(float* __restrict__ out) {
    extern __shared__ char dsm[];
    __shared__ int s_ws;
    uint32_t sb0 = smem_u32(dsm);
    uint32_t sbA = (sb0 + 1023u) & ~1023u;
    char* smA = dsm + (sbA - sb0);
    float* sCn = (float*)(smA + 2 * STAGE);
    float* sXn = sCn + 128;
    int t = threadIdx.x;

    while (true) {
        if (t == 0) s_ws = atomicAdd(&g_ctr, 1);
        __syncthreads();
        int ws = s_ws;
        if (ws >= 2 * C_DIM) break;
        int c = ws >> 1;
        if (ws & 1) run_tile<0>(sbA, smA, sCn, sXn, out, c, t);
        else        run_tile<1>(sbA, smA, sCn, sXn, out, c, t);
    }
}

// ---------------------------------------------------------------------------
extern "C" void kernel_launch(void* const* d_in, const int* in_sizes, int n_in,
                              void* d_out, int out_size) {
    const float* x   = (const float*)d_in[0];
    const float* lnw = (const float*)d_in[1];
    const float* lnb = (const float*)d_in[2];
    const float* cc  = (const float*)d_in[3];
    float* out = (float*)d_out;

    const int SMEM = 2 * STAGE + 1024 + 1024;      // 133,120 B

    cudaFuncSetAttribute(dist_gemm_all, cudaFuncAttributeMaxDynamicSharedMemorySize, SMEM);

    ln_split_kernel<<<dim3(BD, 2), 256>>>(x, lnw, lnb);
    cc_split_kernel<<<C_DIM * CN / 8, 256>>>(cc);
    dist_gemm_all<<<148, 512, SMEM>>>(out);
}

// round 7
// speedup vs baseline: 1.1027x; 1.0841x over previous
#include <cuda_runtime.h>
#include <cuda_bf16.h>
#include <cstdint>

#define C_DIM 256
#define BD    128
#define CN    128
#define KREAL 784
#define KP    832           // padded K (13 * 64)
#define NTILE 26            // KP / 32
#define ALPHA 32.0f

// Split bf16 scratch: [C][128][KP] hi/lo for x and cc (54.5MB each)
#define NU4 3407872
__device__ uint4 g_xh[NU4];
__device__ uint4 g_xl[NU4];
__device__ uint4 g_ch[NU4];
__device__ uint4 g_cl[NU4];
__device__ float g_xn[NTILE * C_DIM * BD];   // |x|^2 per-tile partials (c, bd)
__device__ float g_cn[C_DIM * CN];           // |cc|^2 per (c, cn)
__device__ int   g_ctr;                      // work queue (reset by ln_split)

__device__ __forceinline__ uint32_t smem_u32(const void* p) {
    uint32_t a;
    asm("{ .reg .u64 t; cvta.to.shared.u64 t, %1; cvt.u32.u64 %0, t; }" : "=r"(a) : "l"(p));
    return a;
}

#define SWZ(off) ((off) ^ (((off) >> 3) & 0x70))

#define CP16(dst, src) \
    asm volatile("cp.async.cg.shared.global [%0], [%1], 16;" :: "r"(dst), "l"(src))
#define CP_COMMIT() asm volatile("cp.async.commit_group;" ::: "memory")

#define LDSM4(r0, r1, r2, r3, addr) \
    asm volatile("ldmatrix.sync.aligned.m8n8.x4.shared.b16 {%0,%1,%2,%3}, [%4];" \
                 : "=r"(r0), "=r"(r1), "=r"(r2), "=r"(r3) : "r"(addr))

#define MMA16816(d, a, b) \
    asm volatile("mma.sync.aligned.m16n8k16.row.col.f32.bf16.bf16.f32 " \
                 "{%0,%1,%2,%3},{%4,%5,%6,%7},{%8,%9},{%0,%1,%2,%3};" \
                 : "+f"((d)[0]), "+f"((d)[1]), "+f"((d)[2]), "+f"((d)[3]) \
                 : "r"((a)[0]), "r"((a)[1]), "r"((a)[2]), "r"((a)[3]), \
                   "r"((b)[0]), "r"((b)[1]))

// ---------------------------------------------------------------------------
// Kernel 1: LayerNorm over C + transpose + bf16 hi/lo split + |x|^2 partials.
// grid (BD, 26): ONE 32-hw tile per CTA for occupancy.
// ---------------------------------------------------------------------------
__global__ void ln_split_kernel(const float* __restrict__ x,
                                const float* __restrict__ lnw,
                                const float* __restrict__ lnb) {
    __shared__ float s[32][C_DIM + 1];
    int bd   = blockIdx.x;
    int tile = blockIdx.y;
    int hw0  = tile * 32;
    int lane = threadIdx.x & 31;
    int warp = threadIdx.x >> 5;
    if (bd == 0 && tile == 0 && threadIdx.x == 0) g_ctr = 0;

    #pragma unroll
    for (int i = 0; i < 4; i++) {
        int p  = warp * 4 + i;
        int hw = hw0 + p;
        int c0 = lane * 4, c1 = 128 + lane * 4;
        if (hw < KREAL) {
            const float4* row = (const float4*)(x + ((size_t)bd * KREAL + hw) * C_DIM);
            float4 v0 = row[lane];
            float4 v1 = row[lane + 32];
            float s1 = v0.x + v0.y + v0.z + v0.w + v1.x + v1.y + v1.z + v1.w;
            float s2 = v0.x*v0.x + v0.y*v0.y + v0.z*v0.z + v0.w*v0.w
                     + v1.x*v1.x + v1.y*v1.y + v1.z*v1.z + v1.w*v1.w;
            #pragma unroll
            for (int o = 16; o > 0; o >>= 1) {
                s1 += __shfl_xor_sync(0xffffffffu, s1, o);
                s2 += __shfl_xor_sync(0xffffffffu, s2, o);
            }
            float mean = s1 * (1.0f / C_DIM);
            float var  = s2 * (1.0f / C_DIM) - mean * mean;
            float rs   = rsqrtf(var + 1e-5f);
            s[p][c0+0] = (v0.x - mean) * rs * lnw[c0+0] + lnb[c0+0];
            s[p][c0+1] = (v0.y - mean) * rs * lnw[c0+1] + lnb[c0+1];
            s[p][c0+2] = (v0.z - mean) * rs * lnw[c0+2] + lnb[c0+2];
            s[p][c0+3] = (v0.w - mean) * rs * lnw[c0+3] + lnb[c0+3];
            s[p][c1+0] = (v1.x - mean) * rs * lnw[c1+0] + lnb[c1+0];
            s[p][c1+1] = (v1.y - mean) * rs * lnw[c1+1] + lnb[c1+1];
            s[p][c1+2] = (v1.z - mean) * rs * lnw[c1+2] + lnb[c1+2];
            s[p][c1+3] = (v1.w - mean) * rs * lnw[c1+3] + lnb[c1+3];
        } else {
            #pragma unroll
            for (int e = 0; e < 4; e++) { s[p][c0+e] = 0.0f; s[p][c1+e] = 0.0f; }
        }
    }
    __syncthreads();

    __nv_bfloat16* xh = (__nv_bfloat16*)g_xh;
    __nv_bfloat16* xl = (__nv_bfloat16*)g_xl;
    float nacc[4] = {0.f, 0.f, 0.f, 0.f};

    #pragma unroll
    for (int pass = 0; pass < 4; pass++) {
        int c  = warp * 32 + pass * 8 + (lane >> 2);
        int h0 = (lane & 3) * 8;
        unsigned short hs[8], ls[8];
        #pragma unroll
        for (int h = 0; h < 8; h++) {
            float v = s[h0 + h][c];
            nacc[pass] = fmaf(v, v, nacc[pass]);
            __nv_bfloat16 hb = __float2bfloat16(v);
            hs[h] = __bfloat16_as_ushort(hb);
            ls[h] = __bfloat16_as_ushort(__float2bfloat16(v - __bfloat162float(hb)));
        }
        size_t idx = (size_t)c * (BD * KP) + (size_t)bd * KP + hw0 + h0;
        *(uint4*)(xh + idx) = *(uint4*)hs;
        *(uint4*)(xl + idx) = *(uint4*)ls;
    }

    #pragma unroll
    for (int pass = 0; pass < 4; pass++) {
        float v = nacc[pass];
        v += __shfl_xor_sync(0xffffffffu, v, 1);
        v += __shfl_xor_sync(0xffffffffu, v, 2);
        if ((lane & 3) == 0) {
            int c = warp * 32 + pass * 8 + (lane >> 2);
            g_xn[(size_t)tile * (C_DIM * BD) + (size_t)c * BD + bd] = v;
        }
    }
}

// ---------------------------------------------------------------------------
// Kernel 2: cc fp32 -> bf16 hi/lo split + pad + |cc|^2. One warp per row.
// ---------------------------------------------------------------------------
__global__ void cc_split_kernel(const float* __restrict__ cc) {
    int row  = blockIdx.x * 8 + (threadIdx.x >> 5);
    int lane = threadIdx.x & 31;
    const float4* src = (const float4*)(cc + (size_t)row * KREAL);
    __nv_bfloat16* ch = (__nv_bfloat16*)g_ch;
    __nv_bfloat16* cl = (__nv_bfloat16*)g_cl;
    float ssq = 0.0f;
    #pragma unroll
    for (int i = 0; i < 7; i++) {
        int k4 = lane + 32 * i;
        if (k4 >= KP / 4) break;
        float4 v = (k4 < KREAL / 4) ? src[k4] : make_float4(0.f, 0.f, 0.f, 0.f);
        ssq += v.x*v.x + v.y*v.y + v.z*v.z + v.w*v.w;
        ushort4 hs, ls;
        float e; __nv_bfloat16 h;
        e = v.x; h = __float2bfloat16(e); hs.x = __bfloat16_as_ushort(h);
        ls.x = __bfloat16_as_ushort(__float2bfloat16(e - __bfloat162float(h)));
        e = v.y; h = __float2bfloat16(e); hs.y = __bfloat16_as_ushort(h);
        ls.y = __bfloat16_as_ushort(__float2bfloat16(e - __bfloat162float(h)));
        e = v.z; h = __float2bfloat16(e); hs.z = __bfloat16_as_ushort(h);
        ls.z = __bfloat16_as_ushort(__float2bfloat16(e - __bfloat162float(h)));
        e = v.w; h = __float2bfloat16(e); hs.w = __bfloat16_as_ushort(h);
        ls.w = __bfloat16_as_ushort(__float2bfloat16(e - __bfloat162float(h)));
        size_t o = (size_t)row * KP + (size_t)k4 * 4;
        *(ushort4*)(ch + o) = hs;
        *(ushort4*)(cl + o) = ls;
    }
    #pragma unroll
    for (int o = 16; o > 0; o >>= 1) ssq += __shfl_xor_sync(0xffffffffu, ssq, o);
    if (lane == 0) g_cn[row] = ssq;
}

// ---------------------------------------------------------------------------
// Persistent FUSED distance GEMM: one queue item per c computes BOTH
//   x-dist (A=cc, B=x) with fused softmax, and cc-dist (A=cc, B=A in place).
// 512 threads, warp grid 4m x 4n (32x32 per warp per output), K=832,
// double-buffered 64KB stages (A hi/lo 32KB + Bx hi/lo 32KB).
// Per ks: 12 LDSM4 / 48 MMA (ratio 4.0). cc loaded from DRAM once per c.
// ---------------------------------------------------------------------------
#define STAGE  65536
#define OF_AH  0
#define OF_AL  16384
#define OF_BH  32768
#define OF_BL  49152

__global__ void __launch_bounds__(512)
dist_gemm_all(float* __restrict__ out) {
    extern __shared__ char dsm[];
    __shared__ int s_ws;
    uint32_t sb0 = smem_u32(dsm);
    uint32_t sbA = (sb0 + 1023u) & ~1023u;
    char* smA = dsm + (sbA - sb0);
    float* sCn = (float*)(smA + 2 * STAGE);
    float* sXn = sCn + 128;

    const size_t OUT1 = (size_t)BD * C_DIM * CN;
    int t = threadIdx.x, lane = t & 31, w = t >> 5;
    int wm = (w & 3) * 32, wn = (w >> 2) * 32;

    while (true) {
        if (t == 0) s_ws = atomicAdd(&g_ctr, 1);
        __syncthreads();
        int c = s_ws;
        if (c >= C_DIM) break;

        size_t boff = (size_t)c * 13312;             // 128 rows * 104 uint4
        const uint4* Ah = g_ch + boff;
        const uint4* Al = g_cl + boff;
        const uint4* Bh = g_xh + boff;
        const uint4* Bl = g_xl + boff;

        if (t < 128) sCn[t] = g_cn[(size_t)c * CN + t];
        else if (t < 256) {
            int n = t - 128;
            float sv = 0.f;
            #pragma unroll
            for (int p = 0; p < NTILE; p++)
                sv += g_xn[(size_t)p * (C_DIM * BD) + (size_t)c * BD + n];
            sXn[n] = sv;
        }

        auto issue = [&](int kt, int s) {
            uint32_t base = sbA + (uint32_t)s * STAGE;
            #pragma unroll
            for (int j = 0; j < 2; j++) {
                int idx = j * 512 + t;
                int row = idx >> 3, ch = idx & 7;
                size_t go = (size_t)row * 104 + (size_t)kt * 8 + ch;
                uint32_t so = SWZ((uint32_t)idx * 16);
                CP16(base + OF_AH + so, (const void*)(Ah + go));
                CP16(base + OF_AL + so, (const void*)(Al + go));
                CP16(base + OF_BH + so, (const void*)(Bh + go));
                CP16(base + OF_BL + so, (const void*)(Bl + go));
            }
            CP_COMMIT();
        };

        float ax[2][4][4], ac[2][4][4];
        #pragma unroll
        for (int i = 0; i < 2; i++)
            #pragma unroll
            for (int j = 0; j < 4; j++)
                #pragma unroll
                for (int e = 0; e < 4; e++) { ax[i][j][e] = 0.0f; ac[i][j][e] = 0.0f; }

        issue(0, 0);
        issue(1, 1);

        const uint32_t arow = (uint32_t)(wm + (lane & 15));
        const uint32_t rB   = (uint32_t)(wn + ((lane & 16) ? 8 : 0) + (lane & 7));

        for (int i = 0; i < 13; i++) {
            if (i < 12) asm volatile("cp.async.wait_group 1;" ::: "memory");
            else        asm volatile("cp.async.wait_group 0;" ::: "memory");
            __syncthreads();

            uint32_t base = sbA + (uint32_t)(i & 1) * STAGE;
            #pragma unroll
            for (int ks = 0; ks < 4; ks++) {
                uint32_t ah[2][4], al[2][4], bh[4][2], bl[4][2];
                uint32_t kbA = (uint32_t)ks * 32 + ((lane & 16) ? 16u : 0u);
                uint32_t aA  = base + OF_AH + SWZ(arow * 128 + kbA);
                LDSM4(ah[0][0], ah[0][1], ah[0][2], ah[0][3], aA);
                LDSM4(ah[1][0], ah[1][1], ah[1][2], ah[1][3], aA + 2048);
                LDSM4(al[0][0], al[0][1], al[0][2], al[0][3], aA + 16384);
                LDSM4(al[1][0], al[1][1], al[1][2], al[1][3], aA + 16384 + 2048);

                uint32_t kbB = (uint32_t)ks * 32 + ((lane & 8) ? 16u : 0u);
                uint32_t swB = SWZ(rB * 128 + kbB);

                // ---- B = x (x-distance) ----
                uint32_t aB = base + OF_BH + swB;
                LDSM4(bh[0][0], bh[0][1], bh[1][0], bh[1][1], aB);
                LDSM4(bh[2][0], bh[2][1], bh[3][0], bh[3][1], aB + 2048);
                LDSM4(bl[0][0], bl[0][1], bl[1][0], bl[1][1], aB + 16384);
                LDSM4(bl[2][0], bl[2][1], bl[3][0], bl[3][1], aB + 16384 + 2048);
                #pragma unroll
                for (int mt = 0; mt < 2; mt++)
                    #pragma unroll
                    for (int nt = 0; nt < 4; nt++) {
                        MMA16816(ax[mt][nt], ah[mt], bh[nt]);
                        MMA16816(ax[mt][nt], al[mt], bh[nt]);
                        MMA16816(ax[mt][nt], ah[mt], bl[nt]);
                    }

                // ---- B = cc in place (cc-distance) ----
                uint32_t aC = base + OF_AH + swB;
                LDSM4(bh[0][0], bh[0][1], bh[1][0], bh[1][1], aC);
                LDSM4(bh[2][0], bh[2][1], bh[3][0], bh[3][1], aC + 2048);
                LDSM4(bl[0][0], bl[0][1], bl[1][0], bl[1][1], aC + 16384);
                LDSM4(bl[2][0], bl[2][1], bl[3][0], bl[3][1], aC + 16384 + 2048);
                #pragma unroll
                for (int mt = 0; mt < 2; mt++)
                    #pragma unroll
                    for (int nt = 0; nt < 4; nt++) {
                        MMA16816(ac[mt][nt], ah[mt], bh[nt]);
                        MMA16816(ac[mt][nt], al[mt], bh[nt]);
                        MMA16816(ac[mt][nt], ah[mt], bl[nt]);
                    }
            }
            __syncthreads();
            if (i + 2 < 13) issue(i + 2, i & 1);
        }

        // ---- Epilogue 1: x_distance + fused softmax. ebuf[n=bd][m=cn] ----
        float* ebuf = (float*)smA;
        #pragma unroll
        for (int mt = 0; mt < 2; mt++)
            #pragma unroll
            for (int nt = 0; nt < 4; nt++)
                #pragma unroll
                for (int e = 0; e < 4; e++) {
                    int m = wm + mt * 16 + (lane >> 2) + ((e >> 1) << 3);
                    int n = wn + nt * 8 + ((lane & 3) << 1) + (e & 1);
                    float d2 = sCn[m] + sXn[n] - 2.0f * ax[mt][nt][e];
                    ebuf[n * 132 + m] = sqrtf(fmaxf(d2, 1e-12f));
                }
        __syncthreads();

        float* aout = out + OUT1;
        #pragma unroll
        for (int rj = 0; rj < 8; rj++) {
            int r = w * 8 + rj;                      // bd row
            float4 v = *(const float4*)&ebuf[r * 132 + lane * 4];
            *(float4*)(out + ((size_t)r * C_DIM + c) * CN + lane * 4) = v;
            float mn = fminf(fminf(v.x, v.y), fminf(v.z, v.w));
            #pragma unroll
            for (int o = 16; o > 0; o >>= 1) mn = fminf(mn, __shfl_xor_sync(0xffffffffu, mn, o));
            float e0 = __expf(-ALPHA * (v.x - mn));
            float e1 = __expf(-ALPHA * (v.y - mn));
            float e2 = __expf(-ALPHA * (v.z - mn));
            float e3 = __expf(-ALPHA * (v.w - mn));
            float sum = e0 + e1 + e2 + e3;
            #pragma unroll
            for (int o = 16; o > 0; o >>= 1) sum += __shfl_xor_sync(0xffffffffu, sum, o);
            float inv = 1.0f / sum;
            *(float4*)(aout + ((size_t)r * C_DIM + c) * CN + lane * 4) =
                make_float4(e0 * inv, e1 * inv, e2 * inv, e3 * inv);
        }
        __syncthreads();

        // ---- Epilogue 2: cluster_dist. ebuf[n=cn][m=cn] ----
        #pragma unroll
        for (int mt = 0; mt < 2; mt++)
            #pragma unroll
            for (int nt = 0; nt < 4; nt++)
                #pragma unroll
                for (int e = 0; e < 4; e++) {
                    int m = wm + mt * 16 + (lane >> 2) + ((e >> 1) << 3);
                    int n = wn + nt * 8 + ((lane & 3) << 1) + (e & 1);
                    float d2 = sCn[m] + sCn[n] - 2.0f * ac[mt][nt][e];
                    ebuf[n * 132 + m] = sqrtf(fmaxf(d2, 1e-12f));
                }
        __syncthreads();

        float* o2 = out + 2 * OUT1 + (size_t)c * (CN * CN);
        #pragma unroll
        for (int j = 0; j < 8; j++) {
            int idx = j * 512 + t;
            int n = idx >> 5, m4 = idx & 31;
            *(float4*)(o2 + (size_t)n * CN + m4 * 4) = *(const float4*)&ebuf[n * 132 + m4 * 4];
        }
        // next-item __syncthreads (after atomicAdd) guards smem reuse
    }
}

// ---------------------------------------------------------------------------
extern "C" void kernel_launch(void* const* d_in, const int* in_sizes, int n_in,
                              void* d_out, int out_size) {
    const float* x   = (const float*)d_in[0];
    const float* lnw = (const float*)d_in[1];
    const float* lnb = (const float*)d_in[2];
    const float* cc  = (const float*)d_in[3];
    float* out = (float*)d_out;

    const int SMEM = 2 * STAGE + 1024 + 1024;      // 133,120 B

    cudaFuncSetAttribute(dist_gemm_all, cudaFuncAttributeMaxDynamicSharedMemorySize, SMEM);

    ln_split_kernel<<<dim3(BD, NTILE), 256>>>(x, lnw, lnb);
    cc_split_kernel<<<C_DIM * CN / 8, 256>>>(cc);
    dist_gemm_all<<<148, 512, SMEM>>>(out);
}